// round 1
// baseline (speedup 1.0000x reference)
#include <cuda_runtime.h>
#include <math.h>

// Problem dims (fixed per reference)
#define BB 4
#define SS 2048
#define EE 1024
#define DD 128
#define MM (BB * SS)   // 8192 rows

// Scratch for Q,K,V projections: 3 x 8192 x 128 fp32 = 12 MB total.
__device__ float g_q[MM * DD];
__device__ float g_k[MM * DD];
__device__ float g_v[MM * DD];

// ---------------------------------------------------------------------------
// Kernel 1: QKV projection.  out[sel] = x @ w[sel] + b[sel]
// M=8192, K=1024, N=128. Tiles: BM=64, BN=128, BK=32. 256 threads.
// Each thread computes 4x8 outputs: row = ty + 16*i, col = tx + 16*j.
// ---------------------------------------------------------------------------
__global__ __launch_bounds__(256) void qkv_proj_kernel(
    const float* __restrict__ x,
    const float* __restrict__ wq, const float* __restrict__ bq,
    const float* __restrict__ wk, const float* __restrict__ bk,
    const float* __restrict__ wv, const float* __restrict__ bv)
{
    const int sel = blockIdx.y;
    const float* __restrict__ w    = (sel == 0) ? wq : (sel == 1) ? wk : wv;
    const float* __restrict__ bias = (sel == 0) ? bq : (sel == 1) ? bk : bv;
    float* __restrict__ out        = (sel == 0) ? g_q : (sel == 1) ? g_k : g_v;

    const int BM = 64, BK = 32;
    __shared__ float xs[BM][BK + 1];   // +1 pad
    __shared__ float ws[BK][DD];       // stride 128; col-consecutive reads are conflict-free

    const int row0 = blockIdx.x * BM;
    const int tid  = threadIdx.x;
    const int tx   = tid & 15;
    const int ty   = tid >> 4;

    float acc[4][8];
#pragma unroll
    for (int i = 0; i < 4; i++)
#pragma unroll
        for (int j = 0; j < 8; j++) acc[i][j] = 0.f;

    for (int k0 = 0; k0 < EE; k0 += BK) {
        // load x tile: 64x32 (coalesced: consecutive tid -> consecutive c)
#pragma unroll
        for (int i = tid; i < BM * BK; i += 256) {
            int r = i >> 5, c = i & 31;
            xs[r][c] = x[(size_t)(row0 + r) * EE + k0 + c];
        }
        // load w tile: 32x128
#pragma unroll
        for (int i = tid; i < BK * DD; i += 256) {
            int r = i >> 7, c = i & 127;
            ws[r][c] = w[(size_t)(k0 + r) * DD + c];
        }
        __syncthreads();

#pragma unroll
        for (int kk = 0; kk < BK; kk++) {
            float a[4], bv_[8];
#pragma unroll
            for (int i = 0; i < 4; i++) a[i] = xs[ty + 16 * i][kk];
#pragma unroll
            for (int j = 0; j < 8; j++) bv_[j] = ws[kk][tx + 16 * j];
#pragma unroll
            for (int i = 0; i < 4; i++)
#pragma unroll
                for (int j = 0; j < 8; j++) acc[i][j] = fmaf(a[i], bv_[j], acc[i][j]);
        }
        __syncthreads();
    }

#pragma unroll
    for (int j = 0; j < 8; j++) {
        float bj = bias[tx + 16 * j];
#pragma unroll
        for (int i = 0; i < 4; i++) {
            out[(size_t)(row0 + ty + 16 * i) * DD + tx + 16 * j] = acc[i][j] + bj;
        }
    }
}

// ---------------------------------------------------------------------------
// Kernel 2: causal flash attention, fp32.
// Grid: (S/64, B). Block 256 threads. Q tile 64 rows, key tiles of 64.
// Dynamic smem layout (floats):
//   Qs  : 64 * 129
//   KVs : 64 * 129   (K tile, then reused for V tile)
//   Ss  : 64 * 65    (scores -> probabilities)
//   m_s, l_s, alpha_s : 64 each
// ---------------------------------------------------------------------------
#define QS_STRIDE 129
#define SS_STRIDE 65

__global__ __launch_bounds__(256) void attn_kernel(float* __restrict__ out)
{
    extern __shared__ float sm[];
    float* Qs      = sm;                          // 64*129
    float* KVs     = Qs + 64 * QS_STRIDE;         // 64*129
    float* Ssm     = KVs + 64 * QS_STRIDE;        // 64*65
    float* m_s     = Ssm + 64 * SS_STRIDE;        // 64
    float* l_s     = m_s + 64;                    // 64
    float* alpha_s = l_s + 64;                    // 64

    const int qt  = blockIdx.x;
    const int b   = blockIdx.y;
    const int tid = threadIdx.x;
    const int tx  = tid & 15;
    const int ty  = tid >> 4;
    const float scale = 0.08838834764831845f;  // 1/sqrt(128)

    const float* __restrict__ qg = g_q + (size_t)b * SS * DD;
    const float* __restrict__ kg = g_k + (size_t)b * SS * DD;
    const float* __restrict__ vg = g_v + (size_t)b * SS * DD;

    // Load Q tile
#pragma unroll
    for (int i = tid; i < 64 * 128; i += 256) {
        int r = i >> 7, c = i & 127;
        Qs[r * QS_STRIDE + c] = qg[(size_t)(qt * 64 + r) * DD + c];
    }
    if (tid < 64) { m_s[tid] = -INFINITY; l_s[tid] = 0.f; }

    float o[4][8];
#pragma unroll
    for (int i = 0; i < 4; i++)
#pragma unroll
        for (int j = 0; j < 8; j++) o[i][j] = 0.f;

    __syncthreads();

    for (int kt = 0; kt <= qt; kt++) {
        // ---- load K tile ----
#pragma unroll
        for (int i = tid; i < 64 * 128; i += 256) {
            int r = i >> 7, c = i & 127;
            KVs[r * QS_STRIDE + c] = kg[(size_t)(kt * 64 + r) * DD + c];
        }
        __syncthreads();

        // ---- S = Q K^T (64x64), each thread 4x4: row=ty+16i, col=tx+16j ----
        float s[4][4];
#pragma unroll
        for (int i = 0; i < 4; i++)
#pragma unroll
            for (int j = 0; j < 4; j++) s[i][j] = 0.f;

        for (int k = 0; k < 128; k++) {
            float qv[4], kv[4];
#pragma unroll
            for (int i = 0; i < 4; i++) qv[i] = Qs[(ty + 16 * i) * QS_STRIDE + k];
#pragma unroll
            for (int j = 0; j < 4; j++) kv[j] = KVs[(tx + 16 * j) * QS_STRIDE + k];
#pragma unroll
            for (int i = 0; i < 4; i++)
#pragma unroll
                for (int j = 0; j < 4; j++) s[i][j] = fmaf(qv[i], kv[j], s[i][j]);
        }

        // scale + causal mask, write to Ss
#pragma unroll
        for (int i = 0; i < 4; i++) {
            int gr = qt * 64 + ty + 16 * i;
#pragma unroll
            for (int j = 0; j < 4; j++) {
                int gc = kt * 64 + tx + 16 * j;
                float v = s[i][j] * scale;
                if (gc > gr) v = -INFINITY;
                Ssm[(ty + 16 * i) * SS_STRIDE + tx + 16 * j] = v;
            }
        }
        __syncthreads();

        // ---- online softmax update: 4 threads per row ----
        {
            int row = tid >> 2, seg = tid & 3;
            float mx = -INFINITY;
#pragma unroll
            for (int c = 0; c < 16; c++)
                mx = fmaxf(mx, Ssm[row * SS_STRIDE + seg * 16 + c]);
            mx = fmaxf(mx, __shfl_xor_sync(0xffffffffu, mx, 1));
            mx = fmaxf(mx, __shfl_xor_sync(0xffffffffu, mx, 2));
            float m_old = m_s[row];
            float m_new = fmaxf(m_old, mx);
            float sum = 0.f;
#pragma unroll
            for (int c = 0; c < 16; c++) {
                int idx = row * SS_STRIDE + seg * 16 + c;
                float p = __expf(Ssm[idx] - m_new);
                Ssm[idx] = p;
                sum += p;
            }
            sum += __shfl_xor_sync(0xffffffffu, sum, 1);
            sum += __shfl_xor_sync(0xffffffffu, sum, 2);
            if (seg == 0) {
                float alpha = __expf(m_old - m_new);
                alpha_s[row] = alpha;
                l_s[row] = l_s[row] * alpha + sum;
                m_s[row] = m_new;
            }
        }
        __syncthreads();

        // rescale O accumulators
        {
            float al[4];
#pragma unroll
            for (int i = 0; i < 4; i++) al[i] = alpha_s[ty + 16 * i];
#pragma unroll
            for (int i = 0; i < 4; i++)
#pragma unroll
                for (int j = 0; j < 8; j++) o[i][j] *= al[i];
        }

        // ---- load V tile into KVs (all reads of K done by the sync above) ----
#pragma unroll
        for (int i = tid; i < 64 * 128; i += 256) {
            int r = i >> 7, c = i & 127;
            KVs[r * QS_STRIDE + c] = vg[(size_t)(kt * 64 + r) * DD + c];
        }
        __syncthreads();

        // ---- O += P @ V : row=ty+16i, col=tx+16j ----
        for (int kk = 0; kk < 64; kk++) {
            float p[4], vv[8];
#pragma unroll
            for (int i = 0; i < 4; i++) p[i] = Ssm[(ty + 16 * i) * SS_STRIDE + kk];
#pragma unroll
            for (int j = 0; j < 8; j++) vv[j] = KVs[kk * QS_STRIDE + tx + 16 * j];
#pragma unroll
            for (int i = 0; i < 4; i++)
#pragma unroll
                for (int j = 0; j < 8; j++) o[i][j] = fmaf(p[i], vv[j], o[i][j]);
        }
        __syncthreads();   // before next iter overwrites KVs / Ss
    }

    // ---- finalize: divide by l, write out ----
    float linv[4];
#pragma unroll
    for (int i = 0; i < 4; i++) linv[i] = 1.f / l_s[ty + 16 * i];
#pragma unroll
    for (int i = 0; i < 4; i++) {
        int gr = qt * 64 + ty + 16 * i;
#pragma unroll
        for (int j = 0; j < 8; j++) {
            out[((size_t)b * SS + gr) * DD + tx + 16 * j] = o[i][j] * linv[i];
        }
    }
}

// ---------------------------------------------------------------------------
// Launch
// ---------------------------------------------------------------------------
extern "C" void kernel_launch(void* const* d_in, const int* in_sizes, int n_in,
                              void* d_out, int out_size)
{
    const float* x  = (const float*)d_in[0];
    const float* wq = (const float*)d_in[1];
    const float* bq = (const float*)d_in[2];
    const float* wk = (const float*)d_in[3];
    const float* bk = (const float*)d_in[4];
    const float* wv = (const float*)d_in[5];
    const float* bv = (const float*)d_in[6];
    float* out = (float*)d_out;

    // QKV projection: 128 row-tiles x 3 selectors
    dim3 pgrid(MM / 64, 3);
    qkv_proj_kernel<<<pgrid, 256>>>(x, wq, bq, wk, bk, wv, bv);

    // Attention
    const int smem_bytes = (2 * 64 * QS_STRIDE + 64 * SS_STRIDE + 3 * 64) * (int)sizeof(float);
    cudaFuncSetAttribute(attn_kernel, cudaFuncAttributeMaxDynamicSharedMemorySize, smem_bytes);
    dim3 agrid(SS / 64, BB);
    attn_kernel<<<agrid, 256, smem_bytes>>>(out);
}

// round 2
// speedup vs baseline: 1.5567x; 1.5567x over previous
#include <cuda_runtime.h>
#include <math.h>

#define BB 4
#define SS 2048
#define EE 1024
#define DD 128
#define MM (BB * SS)   // 8192 rows

// Scratch: projections + split-K partials
__device__ float g_q[MM * DD];
__device__ float g_k[MM * DD];
__device__ float g_v[MM * DD];
__device__ float g_opart[2][MM * DD];   // unnormalized partial O
__device__ float g_mpart[2][MM];
__device__ float g_lpart[2][MM];

// ---------------------------------------------------------------------------
// tf32 helpers
// ---------------------------------------------------------------------------
__device__ __forceinline__ float f2tf32(float x) {
    unsigned u;
    asm("cvt.rna.tf32.f32 %0, %1;" : "=r"(u) : "f"(x));
    return __uint_as_float(u);
}

__device__ __forceinline__ void mma_tf32(float c[4], const unsigned a[4], const unsigned b[2]) {
    asm volatile(
        "mma.sync.aligned.m16n8k8.row.col.f32.tf32.tf32.f32 "
        "{%0,%1,%2,%3},{%4,%5,%6,%7},{%8,%9},{%0,%1,%2,%3};"
        : "+f"(c[0]), "+f"(c[1]), "+f"(c[2]), "+f"(c[3])
        : "r"(a[0]), "r"(a[1]), "r"(a[2]), "r"(a[3]), "r"(b[0]), "r"(b[1]));
}

// ---------------------------------------------------------------------------
// Kernel 1: QKV projection via tf32 tensor cores.
// out[sel] = x @ w[sel] + b[sel].  M=8192, N=128, K=1024.
// Block tile 128x128, 256 threads = 8 warps (4x2), warp tile 32x64.
// ---------------------------------------------------------------------------
#define XS_STRIDE 36   // 32 + 4 pad (float4-aligned)
#define WS_STRIDE 132  // 128 + 4 pad

__global__ __launch_bounds__(256) void qkv_proj_mma(
    const float* __restrict__ x,
    const float* __restrict__ wq, const float* __restrict__ bq,
    const float* __restrict__ wk, const float* __restrict__ bk,
    const float* __restrict__ wv, const float* __restrict__ bv)
{
    const int sel = blockIdx.y;
    const float* __restrict__ w    = (sel == 0) ? wq : (sel == 1) ? wk : wv;
    const float* __restrict__ bias = (sel == 0) ? bq : (sel == 1) ? bk : bv;
    float* __restrict__ out        = (sel == 0) ? g_q : (sel == 1) ? g_k : g_v;

    __shared__ float xs[128 * XS_STRIDE];  // 128 rows x 32 k (tf32)
    __shared__ float ws[32 * WS_STRIDE];   // 32 k x 128 n (tf32)

    const int tid  = threadIdx.x;
    const int lane = tid & 31;
    const int wid  = tid >> 5;
    const int wm   = wid >> 1;     // 0..3
    const int wn   = wid & 1;      // 0..1
    const int g    = lane >> 2;    // 0..7
    const int t    = lane & 3;     // 0..3
    const int row0 = blockIdx.x * 128;

    float acc[2][8][4];
#pragma unroll
    for (int mf = 0; mf < 2; mf++)
#pragma unroll
        for (int nf = 0; nf < 8; nf++)
#pragma unroll
            for (int e = 0; e < 4; e++) acc[mf][nf][e] = 0.f;

    for (int k0 = 0; k0 < EE; k0 += 32) {
        // Load x tile 128x32 (1024 float4 / 256 threads = 4 each)
#pragma unroll
        for (int l = tid; l < 1024; l += 256) {
            int r = l >> 3, c4 = l & 7;
            float4 v = *(const float4*)&x[(size_t)(row0 + r) * EE + k0 + c4 * 4];
            v.x = f2tf32(v.x); v.y = f2tf32(v.y); v.z = f2tf32(v.z); v.w = f2tf32(v.w);
            *(float4*)&xs[r * XS_STRIDE + c4 * 4] = v;
        }
        // Load w tile 32x128
#pragma unroll
        for (int l = tid; l < 1024; l += 256) {
            int r = l >> 5, c4 = l & 31;
            float4 v = *(const float4*)&w[(size_t)(k0 + r) * DD + c4 * 4];
            v.x = f2tf32(v.x); v.y = f2tf32(v.y); v.z = f2tf32(v.z); v.w = f2tf32(v.w);
            *(float4*)&ws[r * WS_STRIDE + c4 * 4] = v;
        }
        __syncthreads();

#pragma unroll
        for (int ks = 0; ks < 4; ks++) {
            const int kk = ks * 8;
            unsigned a[2][4];
#pragma unroll
            for (int mf = 0; mf < 2; mf++) {
                int r = wm * 32 + mf * 16;
                a[mf][0] = __float_as_uint(xs[(r + g) * XS_STRIDE + kk + t]);
                a[mf][1] = __float_as_uint(xs[(r + g + 8) * XS_STRIDE + kk + t]);
                a[mf][2] = __float_as_uint(xs[(r + g) * XS_STRIDE + kk + t + 4]);
                a[mf][3] = __float_as_uint(xs[(r + g + 8) * XS_STRIDE + kk + t + 4]);
            }
            unsigned b[8][2];
#pragma unroll
            for (int nf = 0; nf < 8; nf++) {
                int col = wn * 64 + nf * 8 + g;
                b[nf][0] = __float_as_uint(ws[(kk + t) * WS_STRIDE + col]);
                b[nf][1] = __float_as_uint(ws[(kk + t + 4) * WS_STRIDE + col]);
            }
#pragma unroll
            for (int mf = 0; mf < 2; mf++)
#pragma unroll
                for (int nf = 0; nf < 8; nf++)
                    mma_tf32(acc[mf][nf], a[mf], b[nf]);
        }
        __syncthreads();
    }

    // Epilogue: bias add + store
#pragma unroll
    for (int mf = 0; mf < 2; mf++) {
        int rbase = row0 + wm * 32 + mf * 16 + g;
#pragma unroll
        for (int nf = 0; nf < 8; nf++) {
            int col = wn * 64 + nf * 8 + t * 2;
            float b0 = __ldg(&bias[col]), b1 = __ldg(&bias[col + 1]);
            float2 v0 = make_float2(acc[mf][nf][0] + b0, acc[mf][nf][1] + b1);
            float2 v1 = make_float2(acc[mf][nf][2] + b0, acc[mf][nf][3] + b1);
            *(float2*)&out[(size_t)rbase * DD + col]       = v0;
            *(float2*)&out[(size_t)(rbase + 8) * DD + col] = v1;
        }
    }
}

// ---------------------------------------------------------------------------
// Kernel 2: causal flash attention, fp32, split-K (chunks of 16 kt-tiles).
// Work unit u in 0..47 (per batch), LPT-ordered:
//   u<17        -> (qt=15+u, c=0)  size 16
//   u==17       -> (qt=31,  c=1)   size 16
//   v=u-18, s=15-v/2:
//     v even    -> (qt=s-1, c=0)   size s
//     v odd     -> (qt=s+15,c=1)   size s
// ---------------------------------------------------------------------------
#define QS_STRIDE 132
#define SS_STRIDE 68

__global__ __launch_bounds__(256, 2) void attn_partial_kernel()
{
    extern __shared__ float sm[];
    float* Qs      = sm;                       // 64*132
    float* KVs     = Qs + 64 * QS_STRIDE;      // 64*132
    float* Ssm     = KVs + 64 * QS_STRIDE;     // 64*68
    float* m_s     = Ssm + 64 * SS_STRIDE;     // 64
    float* l_s     = m_s + 64;                 // 64
    float* alpha_s = l_s + 64;                 // 64

    const int u = blockIdx.x;
    const int b = blockIdx.y;
    int qt, c;
    if (u < 17)      { qt = 15 + u; c = 0; }
    else if (u == 17){ qt = 31;     c = 1; }
    else {
        int v = u - 18;
        int s = 15 - (v >> 1);
        if ((v & 1) == 0) { qt = s - 1;  c = 0; }
        else              { qt = s + 15; c = 1; }
    }
    const int kt_begin = (c == 0) ? 0 : 16;
    const int kt_end   = (c == 0) ? min(qt, 15) : qt;   // inclusive

    const int tid = threadIdx.x;
    const int tx  = tid & 15;
    const int ty  = tid >> 4;
    const int oc0 = (tid & 15) * 8;   // O column base (contiguous 8)
    const float scale = 0.08838834764831845f;  // 1/sqrt(128)

    const float* __restrict__ qg = g_q + (size_t)b * SS * DD;
    const float* __restrict__ kg = g_k + (size_t)b * SS * DD;
    const float* __restrict__ vg = g_v + (size_t)b * SS * DD;

    // Load Q tile (float4: 2048 f4 / 256 = 8 each)
#pragma unroll
    for (int i = tid; i < 2048; i += 256) {
        int r = i >> 5, c4 = i & 31;
        *(float4*)&Qs[r * QS_STRIDE + c4 * 4] =
            *(const float4*)&qg[(size_t)(qt * 64 + r) * DD + c4 * 4];
    }
    if (tid < 64) { m_s[tid] = -INFINITY; l_s[tid] = 0.f; }

    float o[4][8];
#pragma unroll
    for (int i = 0; i < 4; i++)
#pragma unroll
        for (int j = 0; j < 8; j++) o[i][j] = 0.f;

    __syncthreads();

    for (int kt = kt_begin; kt <= kt_end; kt++) {
        // ---- load K tile ----
#pragma unroll
        for (int i = tid; i < 2048; i += 256) {
            int r = i >> 5, c4 = i & 31;
            *(float4*)&KVs[r * QS_STRIDE + c4 * 4] =
                *(const float4*)&kg[(size_t)(kt * 64 + r) * DD + c4 * 4];
        }
        __syncthreads();

        // ---- S = Q K^T, thread tile 4x4, float4 over k ----
        float s[4][4];
#pragma unroll
        for (int i = 0; i < 4; i++)
#pragma unroll
            for (int j = 0; j < 4; j++) s[i][j] = 0.f;

#pragma unroll 4
        for (int k4 = 0; k4 < 32; k4++) {
            float4 qv[4], kv[4];
#pragma unroll
            for (int i = 0; i < 4; i++)
                qv[i] = *(const float4*)&Qs[(ty + 16 * i) * QS_STRIDE + k4 * 4];
#pragma unroll
            for (int j = 0; j < 4; j++)
                kv[j] = *(const float4*)&KVs[(tx + 16 * j) * QS_STRIDE + k4 * 4];
#pragma unroll
            for (int i = 0; i < 4; i++)
#pragma unroll
                for (int j = 0; j < 4; j++) {
                    s[i][j] = fmaf(qv[i].x, kv[j].x, s[i][j]);
                    s[i][j] = fmaf(qv[i].y, kv[j].y, s[i][j]);
                    s[i][j] = fmaf(qv[i].z, kv[j].z, s[i][j]);
                    s[i][j] = fmaf(qv[i].w, kv[j].w, s[i][j]);
                }
        }

        // scale + causal mask -> Ss
#pragma unroll
        for (int i = 0; i < 4; i++) {
            int gr = qt * 64 + ty + 16 * i;
#pragma unroll
            for (int j = 0; j < 4; j++) {
                int gc = kt * 64 + tx + 16 * j;
                float v = s[i][j] * scale;
                if (gc > gr) v = -INFINITY;
                Ssm[(ty + 16 * i) * SS_STRIDE + tx + 16 * j] = v;
            }
        }
        __syncthreads();

        // ---- online softmax: 4 threads per row ----
        {
            int row = tid >> 2, seg = tid & 3;
            float mx = -INFINITY;
#pragma unroll
            for (int cc = 0; cc < 16; cc++)
                mx = fmaxf(mx, Ssm[row * SS_STRIDE + seg * 16 + cc]);
            mx = fmaxf(mx, __shfl_xor_sync(0xffffffffu, mx, 1));
            mx = fmaxf(mx, __shfl_xor_sync(0xffffffffu, mx, 2));
            float m_old = m_s[row];
            float m_new = fmaxf(m_old, mx);
            float sum = 0.f;
#pragma unroll
            for (int cc = 0; cc < 16; cc++) {
                int idx = row * SS_STRIDE + seg * 16 + cc;
                float p = __expf(Ssm[idx] - m_new);
                Ssm[idx] = p;
                sum += p;
            }
            sum += __shfl_xor_sync(0xffffffffu, sum, 1);
            sum += __shfl_xor_sync(0xffffffffu, sum, 2);
            if (seg == 0) {
                float alpha = __expf(m_old - m_new);
                alpha_s[row] = alpha;
                l_s[row] = l_s[row] * alpha + sum;
                m_s[row] = m_new;
            }
        }
        __syncthreads();

        // rescale O
        {
            float al[4];
#pragma unroll
            for (int i = 0; i < 4; i++) al[i] = alpha_s[ty + 16 * i];
#pragma unroll
            for (int i = 0; i < 4; i++)
#pragma unroll
                for (int j = 0; j < 8; j++) o[i][j] *= al[i];
        }

        // ---- load V tile into KVs ----
#pragma unroll
        for (int i = tid; i < 2048; i += 256) {
            int r = i >> 5, c4 = i & 31;
            *(float4*)&KVs[r * QS_STRIDE + c4 * 4] =
                *(const float4*)&vg[(size_t)(kt * 64 + r) * DD + c4 * 4];
        }
        __syncthreads();

        // ---- O += P @ V : rows ty+16i, cols oc0..oc0+7 (float4 V reads) ----
#pragma unroll 4
        for (int kk = 0; kk < 64; kk++) {
            float p[4];
#pragma unroll
            for (int i = 0; i < 4; i++) p[i] = Ssm[(ty + 16 * i) * SS_STRIDE + kk];
            float4 v0 = *(const float4*)&KVs[kk * QS_STRIDE + oc0];
            float4 v1 = *(const float4*)&KVs[kk * QS_STRIDE + oc0 + 4];
#pragma unroll
            for (int i = 0; i < 4; i++) {
                o[i][0] = fmaf(p[i], v0.x, o[i][0]);
                o[i][1] = fmaf(p[i], v0.y, o[i][1]);
                o[i][2] = fmaf(p[i], v0.z, o[i][2]);
                o[i][3] = fmaf(p[i], v0.w, o[i][3]);
                o[i][4] = fmaf(p[i], v1.x, o[i][4]);
                o[i][5] = fmaf(p[i], v1.y, o[i][5]);
                o[i][6] = fmaf(p[i], v1.z, o[i][6]);
                o[i][7] = fmaf(p[i], v1.w, o[i][7]);
            }
        }
        __syncthreads();
    }

    // ---- write partial (unnormalized O, m, l) ----
    float* op = g_opart[c];
#pragma unroll
    for (int i = 0; i < 4; i++) {
        size_t row = (size_t)b * SS + qt * 64 + ty + 16 * i;
        *(float4*)&op[row * DD + oc0]     = make_float4(o[i][0], o[i][1], o[i][2], o[i][3]);
        *(float4*)&op[row * DD + oc0 + 4] = make_float4(o[i][4], o[i][5], o[i][6], o[i][7]);
    }
    if (tid < 64) {
        size_t row = (size_t)b * SS + qt * 64 + tid;
        g_mpart[c][row] = m_s[tid];
        g_lpart[c][row] = l_s[tid];
    }
}

// ---------------------------------------------------------------------------
// Kernel 3: combine partials.  Rows with in-batch index >= 1024 have 2 chunks.
// One float4 per thread: 262144 threads.
// ---------------------------------------------------------------------------
__global__ __launch_bounds__(256) void attn_reduce_kernel(float* __restrict__ out)
{
    int gid = blockIdx.x * 256 + threadIdx.x;   // 0 .. MM*DD/4-1
    int row = gid >> 5;                          // 32 float4 per row
    int rib = row & (SS - 1);                    // row in batch

    float4 o0 = *(const float4*)&g_opart[0][gid * 4];
    float m0 = g_mpart[0][row];
    float l0 = g_lpart[0][row];

    float4 r;
    if (rib >= 1024) {
        float4 o1 = *(const float4*)&g_opart[1][gid * 4];
        float m1 = g_mpart[1][row];
        float l1 = g_lpart[1][row];
        float m  = fmaxf(m0, m1);
        float w0 = __expf(m0 - m);
        float w1 = __expf(m1 - m);
        float inv = 1.f / (w0 * l0 + w1 * l1);
        r.x = (w0 * o0.x + w1 * o1.x) * inv;
        r.y = (w0 * o0.y + w1 * o1.y) * inv;
        r.z = (w0 * o0.z + w1 * o1.z) * inv;
        r.w = (w0 * o0.w + w1 * o1.w) * inv;
    } else {
        float inv = 1.f / l0;
        r.x = o0.x * inv; r.y = o0.y * inv; r.z = o0.z * inv; r.w = o0.w * inv;
    }
    *(float4*)&out[gid * 4] = r;
}

// ---------------------------------------------------------------------------
// Launch
// ---------------------------------------------------------------------------
extern "C" void kernel_launch(void* const* d_in, const int* in_sizes, int n_in,
                              void* d_out, int out_size)
{
    const float* x  = (const float*)d_in[0];
    const float* wq = (const float*)d_in[1];
    const float* bq = (const float*)d_in[2];
    const float* wk = (const float*)d_in[3];
    const float* bk = (const float*)d_in[4];
    const float* wv = (const float*)d_in[5];
    const float* bv = (const float*)d_in[6];
    float* out = (float*)d_out;

    // QKV projection: tf32 tensor cores
    dim3 pgrid(MM / 128, 3);
    qkv_proj_mma<<<pgrid, 256>>>(x, wq, bq, wk, bk, wv, bv);

    // Attention partials (split-K, LPT order)
    const int smem_bytes = (2 * 64 * QS_STRIDE + 64 * SS_STRIDE + 3 * 64) * (int)sizeof(float);
    cudaFuncSetAttribute(attn_partial_kernel, cudaFuncAttributeMaxDynamicSharedMemorySize, smem_bytes);
    dim3 agrid(48, BB);
    attn_partial_kernel<<<agrid, 256, smem_bytes>>>();

    // Combine
    attn_reduce_kernel<<<(MM * DD / 4) / 256, 256>>>(out);
}

// round 3
// speedup vs baseline: 3.0388x; 1.9521x over previous
#include <cuda_runtime.h>
#include <math.h>

#define BB 4
#define SS 2048
#define EE 1024
#define DD 128
#define MM (BB * SS)   // 8192 rows

// Scratch: projections + split-K partials
__device__ float g_q[MM * DD];
__device__ float g_k[MM * DD];
__device__ float g_v[MM * DD];
__device__ float g_opart[2][MM * DD];   // unnormalized partial O
__device__ float g_mpart[2][MM];
__device__ float g_lpart[2][MM];

// ---------------------------------------------------------------------------
// tf32 helpers
// ---------------------------------------------------------------------------
__device__ __forceinline__ float f2tf32(float x) {
    unsigned u;
    asm("cvt.rna.tf32.f32 %0, %1;" : "=r"(u) : "f"(x));
    return __uint_as_float(u);
}

__device__ __forceinline__ void mma_tf32(float c[4], const unsigned a[4], const unsigned b[2]) {
    asm volatile(
        "mma.sync.aligned.m16n8k8.row.col.f32.tf32.tf32.f32 "
        "{%0,%1,%2,%3},{%4,%5,%6,%7},{%8,%9},{%0,%1,%2,%3};"
        : "+f"(c[0]), "+f"(c[1]), "+f"(c[2]), "+f"(c[3])
        : "r"(a[0]), "r"(a[1]), "r"(a[2]), "r"(a[3]), "r"(b[0]), "r"(b[1]));
}

// ---------------------------------------------------------------------------
// Kernel 1: QKV projection via tf32 tensor cores. (unchanged from round 2)
// ---------------------------------------------------------------------------
#define XS_STRIDE 36
#define WS_STRIDE 132

__global__ __launch_bounds__(256) void qkv_proj_mma(
    const float* __restrict__ x,
    const float* __restrict__ wq, const float* __restrict__ bq,
    const float* __restrict__ wk, const float* __restrict__ bk,
    const float* __restrict__ wv, const float* __restrict__ bv)
{
    const int sel = blockIdx.y;
    const float* __restrict__ w    = (sel == 0) ? wq : (sel == 1) ? wk : wv;
    const float* __restrict__ bias = (sel == 0) ? bq : (sel == 1) ? bk : bv;
    float* __restrict__ out        = (sel == 0) ? g_q : (sel == 1) ? g_k : g_v;

    __shared__ float xs[128 * XS_STRIDE];
    __shared__ float ws[32 * WS_STRIDE];

    const int tid  = threadIdx.x;
    const int lane = tid & 31;
    const int wid  = tid >> 5;
    const int wm   = wid >> 1;
    const int wn   = wid & 1;
    const int g    = lane >> 2;
    const int t    = lane & 3;
    const int row0 = blockIdx.x * 128;

    float acc[2][8][4];
#pragma unroll
    for (int mf = 0; mf < 2; mf++)
#pragma unroll
        for (int nf = 0; nf < 8; nf++)
#pragma unroll
            for (int e = 0; e < 4; e++) acc[mf][nf][e] = 0.f;

    for (int k0 = 0; k0 < EE; k0 += 32) {
#pragma unroll
        for (int l = tid; l < 1024; l += 256) {
            int r = l >> 3, c4 = l & 7;
            float4 v = *(const float4*)&x[(size_t)(row0 + r) * EE + k0 + c4 * 4];
            v.x = f2tf32(v.x); v.y = f2tf32(v.y); v.z = f2tf32(v.z); v.w = f2tf32(v.w);
            *(float4*)&xs[r * XS_STRIDE + c4 * 4] = v;
        }
#pragma unroll
        for (int l = tid; l < 1024; l += 256) {
            int r = l >> 5, c4 = l & 31;
            float4 v = *(const float4*)&w[(size_t)(k0 + r) * DD + c4 * 4];
            v.x = f2tf32(v.x); v.y = f2tf32(v.y); v.z = f2tf32(v.z); v.w = f2tf32(v.w);
            *(float4*)&ws[r * WS_STRIDE + c4 * 4] = v;
        }
        __syncthreads();

#pragma unroll
        for (int ks = 0; ks < 4; ks++) {
            const int kk = ks * 8;
            unsigned a[2][4];
#pragma unroll
            for (int mf = 0; mf < 2; mf++) {
                int r = wm * 32 + mf * 16;
                a[mf][0] = __float_as_uint(xs[(r + g) * XS_STRIDE + kk + t]);
                a[mf][1] = __float_as_uint(xs[(r + g + 8) * XS_STRIDE + kk + t]);
                a[mf][2] = __float_as_uint(xs[(r + g) * XS_STRIDE + kk + t + 4]);
                a[mf][3] = __float_as_uint(xs[(r + g + 8) * XS_STRIDE + kk + t + 4]);
            }
            unsigned b[8][2];
#pragma unroll
            for (int nf = 0; nf < 8; nf++) {
                int col = wn * 64 + nf * 8 + g;
                b[nf][0] = __float_as_uint(ws[(kk + t) * WS_STRIDE + col]);
                b[nf][1] = __float_as_uint(ws[(kk + t + 4) * WS_STRIDE + col]);
            }
#pragma unroll
            for (int mf = 0; mf < 2; mf++)
#pragma unroll
                for (int nf = 0; nf < 8; nf++)
                    mma_tf32(acc[mf][nf], a[mf], b[nf]);
        }
        __syncthreads();
    }

#pragma unroll
    for (int mf = 0; mf < 2; mf++) {
        int rbase = row0 + wm * 32 + mf * 16 + g;
#pragma unroll
        for (int nf = 0; nf < 8; nf++) {
            int col = wn * 64 + nf * 8 + t * 2;
            float b0 = __ldg(&bias[col]), b1 = __ldg(&bias[col + 1]);
            float2 v0 = make_float2(acc[mf][nf][0] + b0, acc[mf][nf][1] + b1);
            float2 v1 = make_float2(acc[mf][nf][2] + b0, acc[mf][nf][3] + b1);
            *(float2*)&out[(size_t)rbase * DD + col]       = v0;
            *(float2*)&out[(size_t)(rbase + 8) * DD + col] = v1;
        }
    }
}

// ---------------------------------------------------------------------------
// Kernel 2: causal flash attention with tf32 tensor-core MMAs.
// Split-K (chunks of <=16 kt-tiles) with LPT ordering, as round 2.
// 256 threads = 8 warps (4m x 2n).
//   S = Q K^T (64x64): warp tile 16x32, 4 n-frags, 16 k-steps.
//   O += P V  (64x128): warp tile 16x64, 8 n-frags, 8 k-steps.
// Softmax on S fragments in registers; cross-warp row stats via smem.
// ---------------------------------------------------------------------------
#define QS_STRIDE 132
#define PS_STRIDE 68

__global__ __launch_bounds__(256, 2) void attn_partial_kernel()
{
    extern __shared__ float sm[];
    float* Qs      = sm;                       // 64*132 (scale folded in, tf32)
    float* KVs     = Qs + 64 * QS_STRIDE;      // 64*132 (K tile, then V tile; tf32)
    float* Ps      = KVs + 64 * QS_STRIDE;     // 64*68  (probabilities, tf32)
    float* hm      = Ps + 64 * PS_STRIDE;      // 64*2 half-row max
    float* hs      = hm + 128;                 // 64*2 half-row sum
    float* m_s     = hs + 128;                 // 64
    float* l_s     = m_s + 64;                 // 64
    float* alpha_s = l_s + 64;                 // 64

    const int u = blockIdx.x;
    const int b = blockIdx.y;
    int qt, c;
    if (u < 17)      { qt = 15 + u; c = 0; }
    else if (u == 17){ qt = 31;     c = 1; }
    else {
        int v = u - 18;
        int s = 15 - (v >> 1);
        if ((v & 1) == 0) { qt = s - 1;  c = 0; }
        else              { qt = s + 15; c = 1; }
    }
    const int kt_begin = (c == 0) ? 0 : 16;
    const int kt_end   = (c == 0) ? min(qt, 15) : qt;   // inclusive

    const int tid  = threadIdx.x;
    const int lane = tid & 31;
    const int wid  = tid >> 5;
    const int wm   = wid >> 1;     // 0..3
    const int wn   = wid & 1;      // 0..1
    const int g    = lane >> 2;    // 0..7
    const int t    = lane & 3;     // 0..3
    const float scale = 0.08838834764831845f;  // 1/sqrt(128)

    const float* __restrict__ qg = g_q + (size_t)b * SS * DD;
    const float* __restrict__ kg = g_k + (size_t)b * SS * DD;
    const float* __restrict__ vg = g_v + (size_t)b * SS * DD;

    // Load Q tile, scale folded, tf32-rounded
#pragma unroll
    for (int i = tid; i < 2048; i += 256) {
        int r = i >> 5, c4 = i & 31;
        float4 v = *(const float4*)&qg[(size_t)(qt * 64 + r) * DD + c4 * 4];
        v.x = f2tf32(v.x * scale); v.y = f2tf32(v.y * scale);
        v.z = f2tf32(v.z * scale); v.w = f2tf32(v.w * scale);
        *(float4*)&Qs[r * QS_STRIDE + c4 * 4] = v;
    }
    if (tid < 64) { m_s[tid] = -INFINITY; l_s[tid] = 0.f; }

    const int rA = wm * 16 + g;     // S/O row pair owned by this thread
    const int rB = rA + 8;

    float o[8][4];                   // O accum: 8 n-frags x (r,c) quad
#pragma unroll
    for (int nf = 0; nf < 8; nf++)
#pragma unroll
        for (int e = 0; e < 4; e++) o[nf][e] = 0.f;

    __syncthreads();

    for (int kt = kt_begin; kt <= kt_end; kt++) {
        __syncthreads();   // S0: previous PV reads of KVs/Ps complete

        // ---- load K tile (tf32) ----
#pragma unroll
        for (int i = tid; i < 2048; i += 256) {
            int r = i >> 5, c4 = i & 31;
            float4 v = *(const float4*)&kg[(size_t)(kt * 64 + r) * DD + c4 * 4];
            v.x = f2tf32(v.x); v.y = f2tf32(v.y); v.z = f2tf32(v.z); v.w = f2tf32(v.w);
            *(float4*)&KVs[r * QS_STRIDE + c4 * 4] = v;
        }
        __syncthreads();   // S1: K ready

        // ---- S = Q K^T via mma: 4 n-frags, 16 k-steps ----
        float s[4][4];
#pragma unroll
        for (int nf = 0; nf < 4; nf++)
#pragma unroll
            for (int e = 0; e < 4; e++) s[nf][e] = 0.f;

#pragma unroll
        for (int ks = 0; ks < 16; ks++) {
            const int kk = ks * 8;
            unsigned a[4];
            a[0] = __float_as_uint(Qs[rA * QS_STRIDE + kk + t]);
            a[1] = __float_as_uint(Qs[rB * QS_STRIDE + kk + t]);
            a[2] = __float_as_uint(Qs[rA * QS_STRIDE + kk + t + 4]);
            a[3] = __float_as_uint(Qs[rB * QS_STRIDE + kk + t + 4]);
#pragma unroll
            for (int nf = 0; nf < 4; nf++) {
                int kvrow = wn * 32 + nf * 8 + g;
                unsigned bb[2];
                bb[0] = __float_as_uint(KVs[kvrow * QS_STRIDE + kk + t]);
                bb[1] = __float_as_uint(KVs[kvrow * QS_STRIDE + kk + t + 4]);
                mma_tf32(s[nf], a, bb);
            }
        }

        // ---- causal mask (scale already folded into Q) ----
        const int grA = qt * 64 + rA;
        const int grB = qt * 64 + rB;
#pragma unroll
        for (int nf = 0; nf < 4; nf++) {
            int gc0 = kt * 64 + wn * 32 + nf * 8 + 2 * t;
            if (gc0 > grA)     s[nf][0] = -INFINITY;
            if (gc0 + 1 > grA) s[nf][1] = -INFINITY;
            if (gc0 > grB)     s[nf][2] = -INFINITY;
            if (gc0 + 1 > grB) s[nf][3] = -INFINITY;
        }

        // ---- half-row max: reduce over nf then quad ----
        float mxA = -INFINITY, mxB = -INFINITY;
#pragma unroll
        for (int nf = 0; nf < 4; nf++) {
            mxA = fmaxf(mxA, fmaxf(s[nf][0], s[nf][1]));
            mxB = fmaxf(mxB, fmaxf(s[nf][2], s[nf][3]));
        }
        mxA = fmaxf(mxA, __shfl_xor_sync(0xffffffffu, mxA, 1));
        mxA = fmaxf(mxA, __shfl_xor_sync(0xffffffffu, mxA, 2));
        mxB = fmaxf(mxB, __shfl_xor_sync(0xffffffffu, mxB, 1));
        mxB = fmaxf(mxB, __shfl_xor_sync(0xffffffffu, mxB, 2));
        if (t == 0) {
            hm[rA * 2 + wn] = mxA;
            hm[rB * 2 + wn] = mxB;
        }
        __syncthreads();   // S2: hm ready, K reads done

        // ---- load V tile into KVs (overlaps exp work) ----
#pragma unroll
        for (int i = tid; i < 2048; i += 256) {
            int r = i >> 5, c4 = i & 31;
            float4 v = *(const float4*)&vg[(size_t)(kt * 64 + r) * DD + c4 * 4];
            v.x = f2tf32(v.x); v.y = f2tf32(v.y); v.z = f2tf32(v.z); v.w = f2tf32(v.w);
            *(float4*)&KVs[r * QS_STRIDE + c4 * 4] = v;
        }

        // ---- m update + exp + P store + half-row sums ----
        {
            float tmA = fmaxf(hm[rA * 2], hm[rA * 2 + 1]);
            float tmB = fmaxf(hm[rB * 2], hm[rB * 2 + 1]);
            float moA = m_s[rA], moB = m_s[rB];
            float mnA = fmaxf(moA, tmA);
            float mnB = fmaxf(moB, tmB);
            if (wn == 0 && t == 0) {
                m_s[rA] = mnA; alpha_s[rA] = __expf(moA - mnA);
                m_s[rB] = mnB; alpha_s[rB] = __expf(moB - mnB);
            }
            float sumA = 0.f, sumB = 0.f;
#pragma unroll
            for (int nf = 0; nf < 4; nf++) {
                int col = wn * 32 + nf * 8 + 2 * t;
                float p0 = __expf(s[nf][0] - mnA);
                float p1 = __expf(s[nf][1] - mnA);
                float p2 = __expf(s[nf][2] - mnB);
                float p3 = __expf(s[nf][3] - mnB);
                sumA += p0 + p1;
                sumB += p2 + p3;
                *(float2*)&Ps[rA * PS_STRIDE + col] = make_float2(f2tf32(p0), f2tf32(p1));
                *(float2*)&Ps[rB * PS_STRIDE + col] = make_float2(f2tf32(p2), f2tf32(p3));
            }
            sumA += __shfl_xor_sync(0xffffffffu, sumA, 1);
            sumA += __shfl_xor_sync(0xffffffffu, sumA, 2);
            sumB += __shfl_xor_sync(0xffffffffu, sumB, 1);
            sumB += __shfl_xor_sync(0xffffffffu, sumB, 2);
            if (t == 0) {
                hs[rA * 2 + wn] = sumA;
                hs[rB * 2 + wn] = sumB;
            }
        }
        __syncthreads();   // S3: Ps, hs, alpha_s, V ready

        if (tid < 64)
            l_s[tid] = l_s[tid] * alpha_s[tid] + hs[tid * 2] + hs[tid * 2 + 1];

        // ---- rescale O ----
        {
            float aA = alpha_s[rA], aB = alpha_s[rB];
#pragma unroll
            for (int nf = 0; nf < 8; nf++) {
                o[nf][0] *= aA; o[nf][1] *= aA;
                o[nf][2] *= aB; o[nf][3] *= aB;
            }
        }

        // ---- O += P V via mma: 8 n-frags, 8 k-steps ----
#pragma unroll
        for (int ks = 0; ks < 8; ks++) {
            const int kk = ks * 8;
            unsigned a[4];
            a[0] = __float_as_uint(Ps[rA * PS_STRIDE + kk + t]);
            a[1] = __float_as_uint(Ps[rB * PS_STRIDE + kk + t]);
            a[2] = __float_as_uint(Ps[rA * PS_STRIDE + kk + t + 4]);
            a[3] = __float_as_uint(Ps[rB * PS_STRIDE + kk + t + 4]);
#pragma unroll
            for (int nf = 0; nf < 8; nf++) {
                int col = wn * 64 + nf * 8 + g;
                unsigned bb[2];
                bb[0] = __float_as_uint(KVs[(kk + t) * QS_STRIDE + col]);
                bb[1] = __float_as_uint(KVs[(kk + t + 4) * QS_STRIDE + col]);
                mma_tf32(o[nf], a, bb);
            }
        }
    }

    // ---- write partial (unnormalized O, m, l) ----
    float* op = g_opart[c];
    {
        size_t rowA = (size_t)b * SS + qt * 64 + rA;
        size_t rowB = (size_t)b * SS + qt * 64 + rB;
#pragma unroll
        for (int nf = 0; nf < 8; nf++) {
            int col = wn * 64 + nf * 8 + 2 * t;
            *(float2*)&op[rowA * DD + col] = make_float2(o[nf][0], o[nf][1]);
            *(float2*)&op[rowB * DD + col] = make_float2(o[nf][2], o[nf][3]);
        }
    }
    if (tid < 64) {
        size_t row = (size_t)b * SS + qt * 64 + tid;
        g_mpart[c][row] = m_s[tid];
        g_lpart[c][row] = l_s[tid];
    }
}

// ---------------------------------------------------------------------------
// Kernel 3: combine partials. (unchanged)
// ---------------------------------------------------------------------------
__global__ __launch_bounds__(256) void attn_reduce_kernel(float* __restrict__ out)
{
    int gid = blockIdx.x * 256 + threadIdx.x;
    int row = gid >> 5;
    int rib = row & (SS - 1);

    float4 o0 = *(const float4*)&g_opart[0][gid * 4];
    float m0 = g_mpart[0][row];
    float l0 = g_lpart[0][row];

    float4 r;
    if (rib >= 1024) {
        float4 o1 = *(const float4*)&g_opart[1][gid * 4];
        float m1 = g_mpart[1][row];
        float l1 = g_lpart[1][row];
        float m  = fmaxf(m0, m1);
        float w0 = __expf(m0 - m);
        float w1 = __expf(m1 - m);
        float inv = 1.f / (w0 * l0 + w1 * l1);
        r.x = (w0 * o0.x + w1 * o1.x) * inv;
        r.y = (w0 * o0.y + w1 * o1.y) * inv;
        r.z = (w0 * o0.z + w1 * o1.z) * inv;
        r.w = (w0 * o0.w + w1 * o1.w) * inv;
    } else {
        float inv = 1.f / l0;
        r.x = o0.x * inv; r.y = o0.y * inv; r.z = o0.z * inv; r.w = o0.w * inv;
    }
    *(float4*)&out[gid * 4] = r;
}

// ---------------------------------------------------------------------------
// Launch
// ---------------------------------------------------------------------------
extern "C" void kernel_launch(void* const* d_in, const int* in_sizes, int n_in,
                              void* d_out, int out_size)
{
    const float* x  = (const float*)d_in[0];
    const float* wq = (const float*)d_in[1];
    const float* bq = (const float*)d_in[2];
    const float* wk = (const float*)d_in[3];
    const float* bk = (const float*)d_in[4];
    const float* wv = (const float*)d_in[5];
    const float* bv = (const float*)d_in[6];
    float* out = (float*)d_out;

    dim3 pgrid(MM / 128, 3);
    qkv_proj_mma<<<pgrid, 256>>>(x, wq, bq, wk, bk, wv, bv);

    const int smem_bytes = (2 * 64 * QS_STRIDE + 64 * PS_STRIDE + 2 * 128 + 3 * 64) * (int)sizeof(float);
    cudaFuncSetAttribute(attn_partial_kernel, cudaFuncAttributeMaxDynamicSharedMemorySize, smem_bytes);
    dim3 agrid(48, BB);
    attn_partial_kernel<<<agrid, 256, smem_bytes>>>();

    attn_reduce_kernel<<<(MM * DD / 4) / 256, 256>>>(out);
}

// round 4
// speedup vs baseline: 4.3517x; 1.4320x over previous
#include <cuda_runtime.h>
#include <math.h>

#define BB 4
#define SS 2048
#define EE 1024
#define DD 128
#define MM (BB * SS)   // 8192 rows

// Scratch: projections + split-K partials (4 chunks of 8 kt-tiles each)
__device__ float g_q[MM * DD];
__device__ float g_k[MM * DD];
__device__ float g_v[MM * DD];
__device__ float g_opart[4][MM * DD];   // unnormalized partial O
__device__ float g_mpart[4][MM];
__device__ float g_lpart[4][MM];

// ---------------------------------------------------------------------------
// tf32 helpers
// ---------------------------------------------------------------------------
__device__ __forceinline__ float f2tf32(float x) {
    unsigned u;
    asm("cvt.rna.tf32.f32 %0, %1;" : "=r"(u) : "f"(x));
    return __uint_as_float(u);
}

__device__ __forceinline__ void mma_tf32(float c[4], const unsigned a[4], const unsigned b[2]) {
    asm volatile(
        "mma.sync.aligned.m16n8k8.row.col.f32.tf32.tf32.f32 "
        "{%0,%1,%2,%3},{%4,%5,%6,%7},{%8,%9},{%0,%1,%2,%3};"
        : "+f"(c[0]), "+f"(c[1]), "+f"(c[2]), "+f"(c[3])
        : "r"(a[0]), "r"(a[1]), "r"(a[2]), "r"(a[3]), "r"(b[0]), "r"(b[1]));
}

// ---------------------------------------------------------------------------
// Kernel 1: QKV projection via tf32 tensor cores.
// BM=64, BN=128, BK=32.  8 warps as 2m x 4n, warp tile 32x32 (mf=2, nf=4).
// Grid (128, 3) = 384 blocks -> single wave at 3 CTAs/SM.
// ---------------------------------------------------------------------------
#define XS_STRIDE 36
#define WS_STRIDE 132

__global__ __launch_bounds__(256, 3) void qkv_proj_mma(
    const float* __restrict__ x,
    const float* __restrict__ wq, const float* __restrict__ bq,
    const float* __restrict__ wk, const float* __restrict__ bk,
    const float* __restrict__ wv, const float* __restrict__ bv)
{
    const int sel = blockIdx.y;
    const float* __restrict__ w    = (sel == 0) ? wq : (sel == 1) ? wk : wv;
    const float* __restrict__ bias = (sel == 0) ? bq : (sel == 1) ? bk : bv;
    float* __restrict__ out        = (sel == 0) ? g_q : (sel == 1) ? g_k : g_v;

    __shared__ float xs[64 * XS_STRIDE];   // 64 rows x 32 k
    __shared__ float ws[32 * WS_STRIDE];   // 32 k x 128 n

    const int tid  = threadIdx.x;
    const int lane = tid & 31;
    const int wid  = tid >> 5;
    const int wm   = wid >> 2;     // 0..1  (32 rows)
    const int wn   = wid & 3;      // 0..3  (32 cols)
    const int g    = lane >> 2;    // 0..7
    const int t    = lane & 3;     // 0..3
    const int row0 = blockIdx.x * 64;

    float acc[2][4][4];
#pragma unroll
    for (int mf = 0; mf < 2; mf++)
#pragma unroll
        for (int nf = 0; nf < 4; nf++)
#pragma unroll
            for (int e = 0; e < 4; e++) acc[mf][nf][e] = 0.f;

    for (int k0 = 0; k0 < EE; k0 += 32) {
        // x tile 64x32 = 512 float4 (2 per thread)
#pragma unroll
        for (int l = tid; l < 512; l += 256) {
            int r = l >> 3, c4 = l & 7;
            float4 v = *(const float4*)&x[(size_t)(row0 + r) * EE + k0 + c4 * 4];
            v.x = f2tf32(v.x); v.y = f2tf32(v.y); v.z = f2tf32(v.z); v.w = f2tf32(v.w);
            *(float4*)&xs[r * XS_STRIDE + c4 * 4] = v;
        }
        // w tile 32x128 = 1024 float4 (4 per thread)
#pragma unroll
        for (int l = tid; l < 1024; l += 256) {
            int r = l >> 5, c4 = l & 31;
            float4 v = *(const float4*)&w[(size_t)(k0 + r) * DD + c4 * 4];
            v.x = f2tf32(v.x); v.y = f2tf32(v.y); v.z = f2tf32(v.z); v.w = f2tf32(v.w);
            *(float4*)&ws[r * WS_STRIDE + c4 * 4] = v;
        }
        __syncthreads();

#pragma unroll
        for (int ks = 0; ks < 4; ks++) {
            const int kk = ks * 8;
            unsigned a[2][4];
#pragma unroll
            for (int mf = 0; mf < 2; mf++) {
                int r = wm * 32 + mf * 16;
                a[mf][0] = __float_as_uint(xs[(r + g) * XS_STRIDE + kk + t]);
                a[mf][1] = __float_as_uint(xs[(r + g + 8) * XS_STRIDE + kk + t]);
                a[mf][2] = __float_as_uint(xs[(r + g) * XS_STRIDE + kk + t + 4]);
                a[mf][3] = __float_as_uint(xs[(r + g + 8) * XS_STRIDE + kk + t + 4]);
            }
            unsigned b[4][2];
#pragma unroll
            for (int nf = 0; nf < 4; nf++) {
                int col = wn * 32 + nf * 8 + g;
                b[nf][0] = __float_as_uint(ws[(kk + t) * WS_STRIDE + col]);
                b[nf][1] = __float_as_uint(ws[(kk + t + 4) * WS_STRIDE + col]);
            }
#pragma unroll
            for (int mf = 0; mf < 2; mf++)
#pragma unroll
                for (int nf = 0; nf < 4; nf++)
                    mma_tf32(acc[mf][nf], a[mf], b[nf]);
        }
        __syncthreads();
    }

#pragma unroll
    for (int mf = 0; mf < 2; mf++) {
        int rbase = row0 + wm * 32 + mf * 16 + g;
#pragma unroll
        for (int nf = 0; nf < 4; nf++) {
            int col = wn * 32 + nf * 8 + t * 2;
            float b0 = __ldg(&bias[col]), b1 = __ldg(&bias[col + 1]);
            float2 v0 = make_float2(acc[mf][nf][0] + b0, acc[mf][nf][1] + b1);
            float2 v1 = make_float2(acc[mf][nf][2] + b0, acc[mf][nf][3] + b1);
            *(float2*)&out[(size_t)rbase * DD + col]       = v0;
            *(float2*)&out[(size_t)(rbase + 8) * DD + col] = v1;
        }
    }
}

// ---------------------------------------------------------------------------
// Kernel 2: causal flash attention with tf32 MMAs, split-K chunks of 8 tiles.
// 80 LPT-ordered units per batch:
//   u<24  -> (qt=8+u,  c=0) size 8      (full chunks, c=0)
//   u<40  -> (qt=16+u-24, c=1) size 8
//   u<48  -> (qt=24+u-40, c=2) size 8
//   u<52  -> c=u-48, qt=8c+7, size 8    (last chunks of size 8)
//   else  -> v=u-52, s=7-v/4, c=v&3, qt=8c+s-1, size s
// ---------------------------------------------------------------------------
#define QS_STRIDE 132
#define PS_STRIDE 68

__global__ __launch_bounds__(256, 2) void attn_partial_kernel()
{
    extern __shared__ float sm[];
    float* Qs      = sm;                       // 64*132
    float* KVs     = Qs + 64 * QS_STRIDE;      // 64*132
    float* Ps      = KVs + 64 * QS_STRIDE;     // 64*68
    float* hm      = Ps + 64 * PS_STRIDE;      // 64*2
    float* hs      = hm + 128;                 // 64*2
    float* m_s     = hs + 128;                 // 64
    float* l_s     = m_s + 64;                 // 64
    float* alpha_s = l_s + 64;                 // 64

    const int u = blockIdx.x;
    const int b = blockIdx.y;
    int qt, c;
    if (u < 24)      { qt = 8 + u;         c = 0; }
    else if (u < 40) { qt = 16 + (u - 24); c = 1; }
    else if (u < 48) { qt = 24 + (u - 40); c = 2; }
    else if (u < 52) { c = u - 48; qt = 8 * c + 7; }
    else { int v = u - 52; int s = 7 - (v >> 2); c = v & 3; qt = 8 * c + s - 1; }
    const int kt_begin = 8 * c;
    const int kt_end   = min(qt, 8 * c + 7);   // inclusive

    const int tid  = threadIdx.x;
    const int lane = tid & 31;
    const int wid  = tid >> 5;
    const int wm   = wid >> 1;     // 0..3
    const int wn   = wid & 1;      // 0..1
    const int g    = lane >> 2;    // 0..7
    const int t    = lane & 3;     // 0..3
    const float scale = 0.08838834764831845f;  // 1/sqrt(128)

    const float* __restrict__ qg = g_q + (size_t)b * SS * DD;
    const float* __restrict__ kg = g_k + (size_t)b * SS * DD;
    const float* __restrict__ vg = g_v + (size_t)b * SS * DD;

    // Load Q tile, scale folded, tf32-rounded
#pragma unroll
    for (int i = tid; i < 2048; i += 256) {
        int r = i >> 5, c4 = i & 31;
        float4 v = *(const float4*)&qg[(size_t)(qt * 64 + r) * DD + c4 * 4];
        v.x = f2tf32(v.x * scale); v.y = f2tf32(v.y * scale);
        v.z = f2tf32(v.z * scale); v.w = f2tf32(v.w * scale);
        *(float4*)&Qs[r * QS_STRIDE + c4 * 4] = v;
    }
    if (tid < 64) { m_s[tid] = -INFINITY; l_s[tid] = 0.f; }

    const int rA = wm * 16 + g;
    const int rB = rA + 8;

    float o[8][4];
#pragma unroll
    for (int nf = 0; nf < 8; nf++)
#pragma unroll
        for (int e = 0; e < 4; e++) o[nf][e] = 0.f;

    __syncthreads();

    for (int kt = kt_begin; kt <= kt_end; kt++) {
        __syncthreads();   // previous PV reads of KVs/Ps complete

        // ---- load K tile ----
#pragma unroll
        for (int i = tid; i < 2048; i += 256) {
            int r = i >> 5, c4 = i & 31;
            float4 v = *(const float4*)&kg[(size_t)(kt * 64 + r) * DD + c4 * 4];
            v.x = f2tf32(v.x); v.y = f2tf32(v.y); v.z = f2tf32(v.z); v.w = f2tf32(v.w);
            *(float4*)&KVs[r * QS_STRIDE + c4 * 4] = v;
        }
        __syncthreads();   // K ready

        // ---- S = Q K^T ----
        float s[4][4];
#pragma unroll
        for (int nf = 0; nf < 4; nf++)
#pragma unroll
            for (int e = 0; e < 4; e++) s[nf][e] = 0.f;

#pragma unroll
        for (int ks = 0; ks < 16; ks++) {
            const int kk = ks * 8;
            unsigned a[4];
            a[0] = __float_as_uint(Qs[rA * QS_STRIDE + kk + t]);
            a[1] = __float_as_uint(Qs[rB * QS_STRIDE + kk + t]);
            a[2] = __float_as_uint(Qs[rA * QS_STRIDE + kk + t + 4]);
            a[3] = __float_as_uint(Qs[rB * QS_STRIDE + kk + t + 4]);
#pragma unroll
            for (int nf = 0; nf < 4; nf++) {
                int kvrow = wn * 32 + nf * 8 + g;
                unsigned bb[2];
                bb[0] = __float_as_uint(KVs[kvrow * QS_STRIDE + kk + t]);
                bb[1] = __float_as_uint(KVs[kvrow * QS_STRIDE + kk + t + 4]);
                mma_tf32(s[nf], a, bb);
            }
        }

        // ---- causal mask ----
        const int grA = qt * 64 + rA;
        const int grB = qt * 64 + rB;
#pragma unroll
        for (int nf = 0; nf < 4; nf++) {
            int gc0 = kt * 64 + wn * 32 + nf * 8 + 2 * t;
            if (gc0 > grA)     s[nf][0] = -INFINITY;
            if (gc0 + 1 > grA) s[nf][1] = -INFINITY;
            if (gc0 > grB)     s[nf][2] = -INFINITY;
            if (gc0 + 1 > grB) s[nf][3] = -INFINITY;
        }

        // ---- half-row max ----
        float mxA = -INFINITY, mxB = -INFINITY;
#pragma unroll
        for (int nf = 0; nf < 4; nf++) {
            mxA = fmaxf(mxA, fmaxf(s[nf][0], s[nf][1]));
            mxB = fmaxf(mxB, fmaxf(s[nf][2], s[nf][3]));
        }
        mxA = fmaxf(mxA, __shfl_xor_sync(0xffffffffu, mxA, 1));
        mxA = fmaxf(mxA, __shfl_xor_sync(0xffffffffu, mxA, 2));
        mxB = fmaxf(mxB, __shfl_xor_sync(0xffffffffu, mxB, 1));
        mxB = fmaxf(mxB, __shfl_xor_sync(0xffffffffu, mxB, 2));
        if (t == 0) {
            hm[rA * 2 + wn] = mxA;
            hm[rB * 2 + wn] = mxB;
        }
        __syncthreads();   // hm ready, K reads done

        // ---- load V tile (overlaps exp) ----
#pragma unroll
        for (int i = tid; i < 2048; i += 256) {
            int r = i >> 5, c4 = i & 31;
            float4 v = *(const float4*)&vg[(size_t)(kt * 64 + r) * DD + c4 * 4];
            v.x = f2tf32(v.x); v.y = f2tf32(v.y); v.z = f2tf32(v.z); v.w = f2tf32(v.w);
            *(float4*)&KVs[r * QS_STRIDE + c4 * 4] = v;
        }

        // ---- m update + exp + P store + half-row sums ----
        {
            float tmA = fmaxf(hm[rA * 2], hm[rA * 2 + 1]);
            float tmB = fmaxf(hm[rB * 2], hm[rB * 2 + 1]);
            float moA = m_s[rA], moB = m_s[rB];
            float mnA = fmaxf(moA, tmA);
            float mnB = fmaxf(moB, tmB);
            if (wn == 0 && t == 0) {
                m_s[rA] = mnA; alpha_s[rA] = __expf(moA - mnA);
                m_s[rB] = mnB; alpha_s[rB] = __expf(moB - mnB);
            }
            float sumA = 0.f, sumB = 0.f;
#pragma unroll
            for (int nf = 0; nf < 4; nf++) {
                int col = wn * 32 + nf * 8 + 2 * t;
                float p0 = __expf(s[nf][0] - mnA);
                float p1 = __expf(s[nf][1] - mnA);
                float p2 = __expf(s[nf][2] - mnB);
                float p3 = __expf(s[nf][3] - mnB);
                sumA += p0 + p1;
                sumB += p2 + p3;
                *(float2*)&Ps[rA * PS_STRIDE + col] = make_float2(f2tf32(p0), f2tf32(p1));
                *(float2*)&Ps[rB * PS_STRIDE + col] = make_float2(f2tf32(p2), f2tf32(p3));
            }
            sumA += __shfl_xor_sync(0xffffffffu, sumA, 1);
            sumA += __shfl_xor_sync(0xffffffffu, sumA, 2);
            sumB += __shfl_xor_sync(0xffffffffu, sumB, 1);
            sumB += __shfl_xor_sync(0xffffffffu, sumB, 2);
            if (t == 0) {
                hs[rA * 2 + wn] = sumA;
                hs[rB * 2 + wn] = sumB;
            }
        }
        __syncthreads();   // Ps, hs, alpha_s, V ready

        if (tid < 64)
            l_s[tid] = l_s[tid] * alpha_s[tid] + hs[tid * 2] + hs[tid * 2 + 1];

        // ---- rescale O ----
        {
            float aA = alpha_s[rA], aB = alpha_s[rB];
#pragma unroll
            for (int nf = 0; nf < 8; nf++) {
                o[nf][0] *= aA; o[nf][1] *= aA;
                o[nf][2] *= aB; o[nf][3] *= aB;
            }
        }

        // ---- O += P V ----
#pragma unroll
        for (int ks = 0; ks < 8; ks++) {
            const int kk = ks * 8;
            unsigned a[4];
            a[0] = __float_as_uint(Ps[rA * PS_STRIDE + kk + t]);
            a[1] = __float_as_uint(Ps[rB * PS_STRIDE + kk + t]);
            a[2] = __float_as_uint(Ps[rA * PS_STRIDE + kk + t + 4]);
            a[3] = __float_as_uint(Ps[rB * PS_STRIDE + kk + t + 4]);
#pragma unroll
            for (int nf = 0; nf < 8; nf++) {
                int col = wn * 64 + nf * 8 + g;
                unsigned bb[2];
                bb[0] = __float_as_uint(KVs[(kk + t) * QS_STRIDE + col]);
                bb[1] = __float_as_uint(KVs[(kk + t + 4) * QS_STRIDE + col]);
                mma_tf32(o[nf], a, bb);
            }
        }
    }

    // ---- write partial ----
    float* op = g_opart[c];
    {
        size_t rowA = (size_t)b * SS + qt * 64 + rA;
        size_t rowB = (size_t)b * SS + qt * 64 + rB;
#pragma unroll
        for (int nf = 0; nf < 8; nf++) {
            int col = wn * 64 + nf * 8 + 2 * t;
            *(float2*)&op[rowA * DD + col] = make_float2(o[nf][0], o[nf][1]);
            *(float2*)&op[rowB * DD + col] = make_float2(o[nf][2], o[nf][3]);
        }
    }
    if (tid < 64) {
        size_t row = (size_t)b * SS + qt * 64 + tid;
        g_mpart[c][row] = m_s[tid];
        g_lpart[c][row] = l_s[tid];
    }
}

// ---------------------------------------------------------------------------
// Kernel 3: combine up to 4 partial chunks per row.
// Row rib has nch = (qt>>3)+1 chunks where qt = rib>>6.
// ---------------------------------------------------------------------------
__global__ __launch_bounds__(256) void attn_reduce_kernel(float* __restrict__ out)
{
    int gid = blockIdx.x * 256 + threadIdx.x;   // one float4 each
    int row = gid >> 5;
    int rib = row & (SS - 1);
    int qt  = rib >> 6;
    int nch = (qt >> 3) + 1;

    float m = -INFINITY;
#pragma unroll 4
    for (int ch = 0; ch < nch; ch++) m = fmaxf(m, g_mpart[ch][row]);

    float l = 0.f;
    float4 acc = make_float4(0.f, 0.f, 0.f, 0.f);
#pragma unroll 4
    for (int ch = 0; ch < nch; ch++) {
        float wgt = __expf(g_mpart[ch][row] - m);
        l += wgt * g_lpart[ch][row];
        float4 o = *(const float4*)&g_opart[ch][gid * 4];
        acc.x += wgt * o.x; acc.y += wgt * o.y;
        acc.z += wgt * o.z; acc.w += wgt * o.w;
    }
    float inv = 1.f / l;
    acc.x *= inv; acc.y *= inv; acc.z *= inv; acc.w *= inv;
    *(float4*)&out[gid * 4] = acc;
}

// ---------------------------------------------------------------------------
// Launch
// ---------------------------------------------------------------------------
extern "C" void kernel_launch(void* const* d_in, const int* in_sizes, int n_in,
                              void* d_out, int out_size)
{
    const float* x  = (const float*)d_in[0];
    const float* wq = (const float*)d_in[1];
    const float* bq = (const float*)d_in[2];
    const float* wk = (const float*)d_in[3];
    const float* bk = (const float*)d_in[4];
    const float* wv = (const float*)d_in[5];
    const float* bv = (const float*)d_in[6];
    float* out = (float*)d_out;

    dim3 pgrid(MM / 64, 3);
    qkv_proj_mma<<<pgrid, 256>>>(x, wq, bq, wk, bk, wv, bv);

    const int smem_bytes = (2 * 64 * QS_STRIDE + 64 * PS_STRIDE + 2 * 128 + 3 * 64) * (int)sizeof(float);
    cudaFuncSetAttribute(attn_partial_kernel, cudaFuncAttributeMaxDynamicSharedMemorySize, smem_bytes);
    dim3 agrid(80, BB);
    attn_partial_kernel<<<agrid, 256, smem_bytes>>>();

    attn_reduce_kernel<<<(MM * DD / 4) / 256, 256>>>(out);
}